// round 11
// baseline (speedup 1.0000x reference)
#include <cuda_runtime.h>
#include <cstdint>

#define B_ 32
#define I_ 1152
#define IH 576          // I/2 per block
#define O_ 10
#define D_ 16
#define H_ 10
#define S_ 922
#define RS (O_ * D_)    // 160: row stride in u

// Cross-kernel buffers (2 deterministic float adds per element max)
__device__ float g_num[B_ * O_ * H_ * D_];
__device__ float g_den[B_ * O_ * H_];
__device__ float g_lossbuf[B_ * O_ * H_];
__device__ float g_vnb[B_ * O_ * I_];
__device__ int   g_is64;

__device__ __forceinline__ float sqrt_approx(float x) {
    float y;
    asm("sqrt.approx.f32 %0, %1;" : "=f"(y) : "f"(x));
    return y;
}

// ---------------------------------------------------------------------------
// K0: zero accumulators + dtype probe (first 64 idx elements: safe bounds)
// ---------------------------------------------------------------------------
__global__ void k0_zero(const unsigned* __restrict__ idx32) {
    int t = blockIdx.x * 256 + threadIdx.x;
    if (t < B_ * O_ * H_ * D_) g_num[t] = 0.f;
    if (t < B_ * O_ * H_) { g_den[t] = 0.f; g_lossbuf[t] = 0.f; }
    if (blockIdx.x == 0 && threadIdx.x < 32) {
        unsigned v = idx32[2 * threadIdx.x + 1]
                   | idx32[2 * (threadIdx.x + 32) + 1];
        unsigned r = __reduce_or_sync(0xffffffffu, v);
        if (threadIdx.x == 0) g_is64 = (r == 0u) ? 1 : 0;
    }
}

// ---------------------------------------------------------------------------
// K1: per (bo, half): vn, mask scatter (range-filtered), masked accumulation
//     -> RED into g_num/g_den; vn -> g_vnb
// ---------------------------------------------------------------------------
__global__ __launch_bounds__(256, 5) void k1_accum(const float* __restrict__ u,
                                                   const int* __restrict__ idx) {
    __shared__ __align__(8) float s_vm[2 * IH];   // (vn, mask) interleaved
    __shared__ float s_num[H_ * D_];
    __shared__ float s_den[H_];

    const int blk = blockIdx.x, bo = blk >> 1, half = blk & 1;
    const int b = bo / O_, o = bo % O_, i0 = half * IH;
    const int tid = threadIdx.x, lane = tid & 31, w = tid >> 5;  // 8 warps
    const float* ub = u + ((size_t)b * I_ * O_ + o) * D_;
    const int is64 = g_is64;

    for (int j = tid; j < IH; j += 256) s_vm[2 * j + 1] = 0.f;
    if (tid < H_ * D_) s_num[tid] = 0.f;

    // vn: quad-reduce of row quarters; also spill to global for K2
#pragma unroll 1
    for (int e = tid; e < IH * 4; e += 256) {       // 9 iterations
        int row = e >> 2, j = e & 3;
        float4 q = *(const float4*)(ub + (size_t)(i0 + row) * RS + j * 4);
        float p = q.x * q.x + q.y * q.y + q.z * q.z + q.w * q.w;
        p += __shfl_xor_sync(0xffffffffu, p, 1);
        p += __shfl_xor_sync(0xffffffffu, p, 2);
        if (j == 0) {
            float vn = sqrt_approx(p);
            s_vm[2 * row] = vn;
            g_vnb[(size_t)bo * I_ + i0 + row] = vn;
        }
    }
    __syncthreads();

    // scatter: read full idx slice, keep indices in [i0, i0+IH)
    if (is64) {
#pragma unroll 1
        for (int s = tid; s < S_; s += 256) {
            int base = ((b * S_ + s) * O_ + o) * H_;
            const int4* p = (const int4*)idx + (base >> 1);
            int4 a0 = p[0], a1 = p[1], a2 = p[2], a3 = p[3], a4 = p[4];
            int i;
            i = a0.x - i0; if ((unsigned)i < IH) atomicOr((unsigned*)&s_vm[2*i+1], 1u<<0);
            i = a0.z - i0; if ((unsigned)i < IH) atomicOr((unsigned*)&s_vm[2*i+1], 1u<<1);
            i = a1.x - i0; if ((unsigned)i < IH) atomicOr((unsigned*)&s_vm[2*i+1], 1u<<2);
            i = a1.z - i0; if ((unsigned)i < IH) atomicOr((unsigned*)&s_vm[2*i+1], 1u<<3);
            i = a2.x - i0; if ((unsigned)i < IH) atomicOr((unsigned*)&s_vm[2*i+1], 1u<<4);
            i = a2.z - i0; if ((unsigned)i < IH) atomicOr((unsigned*)&s_vm[2*i+1], 1u<<5);
            i = a3.x - i0; if ((unsigned)i < IH) atomicOr((unsigned*)&s_vm[2*i+1], 1u<<6);
            i = a3.z - i0; if ((unsigned)i < IH) atomicOr((unsigned*)&s_vm[2*i+1], 1u<<7);
            i = a4.x - i0; if ((unsigned)i < IH) atomicOr((unsigned*)&s_vm[2*i+1], 1u<<8);
            i = a4.z - i0; if ((unsigned)i < IH) atomicOr((unsigned*)&s_vm[2*i+1], 1u<<9);
        }
    } else {
#pragma unroll 1
        for (int s = tid; s < S_; s += 256) {
            int base = ((b * S_ + s) * O_ + o) * H_;
            const int2* p = (const int2*)idx + (base >> 1);
            int2 a0 = p[0], a1 = p[1], a2 = p[2], a3 = p[3], a4 = p[4];
            int i;
            i = a0.x - i0; if ((unsigned)i < IH) atomicOr((unsigned*)&s_vm[2*i+1], 1u<<0);
            i = a0.y - i0; if ((unsigned)i < IH) atomicOr((unsigned*)&s_vm[2*i+1], 1u<<1);
            i = a1.x - i0; if ((unsigned)i < IH) atomicOr((unsigned*)&s_vm[2*i+1], 1u<<2);
            i = a1.y - i0; if ((unsigned)i < IH) atomicOr((unsigned*)&s_vm[2*i+1], 1u<<3);
            i = a2.x - i0; if ((unsigned)i < IH) atomicOr((unsigned*)&s_vm[2*i+1], 1u<<4);
            i = a2.y - i0; if ((unsigned)i < IH) atomicOr((unsigned*)&s_vm[2*i+1], 1u<<5);
            i = a3.x - i0; if ((unsigned)i < IH) atomicOr((unsigned*)&s_vm[2*i+1], 1u<<6);
            i = a3.y - i0; if ((unsigned)i < IH) atomicOr((unsigned*)&s_vm[2*i+1], 1u<<7);
            i = a4.x - i0; if ((unsigned)i < IH) atomicOr((unsigned*)&s_vm[2*i+1], 1u<<8);
            i = a4.y - i0; if ((unsigned)i < IH) atomicOr((unsigned*)&s_vm[2*i+1], 1u<<9);
        }
    }
    __syncthreads();

    // masked accumulation: warp = i-stripe; lane halves own h-halves
    {
        const int d  = lane & 15;
        const int hb = (lane >> 4) * 5;
        float a0 = 0.f, a1 = 0.f, a2 = 0.f, a3 = 0.f, a4 = 0.f;
#pragma unroll 4
        for (int ii = w; ii < IH; ii += 8) {        // 72 iterations
            float2   vm = *(const float2*)&s_vm[2 * ii];
            unsigned m  = __float_as_uint(vm.y) >> hb;
            float    t0 = vm.x * ub[(size_t)(i0 + ii) * RS + d];   // L1/L2 hit
            if (m & 1u)  a0 += t0;
            if (m & 2u)  a1 += t0;
            if (m & 4u)  a2 += t0;
            if (m & 8u)  a3 += t0;
            if (m & 16u) a4 += t0;
        }
        atomicAdd(&s_num[(hb + 0) * D_ + d], a0);
        atomicAdd(&s_num[(hb + 1) * D_ + d], a1);
        atomicAdd(&s_num[(hb + 2) * D_ + d], a2);
        atomicAdd(&s_num[(hb + 3) * D_ + d], a3);
        atomicAdd(&s_num[(hb + 4) * D_ + d], a4);
    }

    // den: warp w -> h=w; warps 0,1 additionally h=8,9
    {
        unsigned bit = 1u << w;
        float dn = 0.f;
#pragma unroll 4
        for (int ii = lane; ii < IH; ii += 32) {
            float2 vm = *(const float2*)&s_vm[2 * ii];
            if (__float_as_uint(vm.y) & bit) dn += vm.x;
        }
#pragma unroll
        for (int off = 16; off > 0; off >>= 1)
            dn += __shfl_down_sync(0xffffffffu, dn, off);
        if (lane == 0) s_den[w] = dn;
        if (w < 2) {
            unsigned bit2 = 1u << (8 + w);
            float d2 = 0.f;
#pragma unroll 4
            for (int ii = lane; ii < IH; ii += 32) {
                float2 vm = *(const float2*)&s_vm[2 * ii];
                if (__float_as_uint(vm.y) & bit2) d2 += vm.x;
            }
#pragma unroll
            for (int off = 16; off > 0; off >>= 1)
                d2 += __shfl_down_sync(0xffffffffu, d2, off);
            if (lane == 0) s_den[8 + w] = d2;
        }
    }
    __syncthreads();

    if (tid < H_ * D_) atomicAdd(&g_num[bo * H_ * D_ + tid], s_num[tid]);
    if (tid < H_)      atomicAdd(&g_den[bo * H_ + tid],      s_den[tid]);
}

// ---------------------------------------------------------------------------
// K2: per (bo, half): Mu from globals, butterfly losses over this i-half,
//     RED partial losses into g_lossbuf
// ---------------------------------------------------------------------------
__global__ __launch_bounds__(256, 5) void k2_loss(const float* __restrict__ u) {
    __shared__ __align__(16) float s_Mu[H_][D_];
    __shared__ float s_mu2[H_];
    __shared__ float s_vn[IH];
    __shared__ float s_loss[8][H_];

    const int blk = blockIdx.x, bo = blk >> 1, half = blk & 1;
    const int b = bo / O_, o = bo % O_, i0 = half * IH;
    const int tid = threadIdx.x, lane = tid & 31, w = tid >> 5;
    const float* ub = u + ((size_t)b * I_ * O_ + o) * D_;

    if (tid < H_ * D_) {
        int h = tid >> 4;
        s_Mu[h][tid & 15] = g_num[bo * H_ * D_ + tid] / g_den[bo * H_ + h];
    }
    for (int j = tid; j < IH; j += 256) s_vn[j] = g_vnb[(size_t)bo * I_ + i0 + j];
    __syncthreads();
    if (tid < H_) {
        float m2 = 0.f;
#pragma unroll
        for (int dd = 0; dd < D_; dd++) { float x = s_Mu[tid][dd]; m2 += x * x; }
        s_mu2[tid] = m2;
    }
    __syncthreads();

    // butterfly losses (verified R10 structure; i-range = this half, g=0..63)
    {
        const int dq   = tid & 3;
        const int g    = tid >> 2;            // 0..63
        const int sel  = lane & 1;
        const int bit1 = (lane >> 1) & 1;

#pragma unroll 1
        for (int grp = 0; grp < 2; grp++) {
            const int hb = grp * 4;
            float4 mq0 = *(const float4*)(&s_Mu[hb + 0][dq * 4]);
            float4 mq1 = *(const float4*)(&s_Mu[hb + 1][dq * 4]);
            float4 mq2 = *(const float4*)(&s_Mu[hb + 2][dq * 4]);
            float4 mq3 = *(const float4*)(&s_Mu[hb + 3][dq * 4]);
            const float u2 = s_mu2[hb + 2 * bit1 + sel];
            float lacc = 0.f;
#pragma unroll 1
            for (int k = 0; k < IH / 64; k++) {       // 9 iterations
                int i = g + k * 64;
                float4 q = *(const float4*)(ub + (size_t)(i0 + i) * RS + dq * 4);
                float  v = s_vn[i];
                float sq = v * v;
                float p0 = q.x * mq0.x + q.y * mq0.y + q.z * mq0.z + q.w * mq0.w;
                float p1 = q.x * mq1.x + q.y * mq1.y + q.z * mq1.z + q.w * mq1.w;
                float p2 = q.x * mq2.x + q.y * mq2.y + q.z * mq2.z + q.w * mq2.w;
                float p3 = q.x * mq3.x + q.y * mq3.y + q.z * mq3.z + q.w * mq3.w;
                float keep_lo = sel ? p1 : p0;
                float send_lo = sel ? p0 : p1;
                float C_lo = keep_lo + __shfl_xor_sync(0xffffffffu, send_lo, 1);
                float keep_hi = sel ? p3 : p2;
                float send_hi = sel ? p2 : p3;
                float C_hi = keep_hi + __shfl_xor_sync(0xffffffffu, send_hi, 1);
                float keep2 = bit1 ? C_hi : C_lo;
                float send2 = bit1 ? C_lo : C_hi;
                float dot = keep2 + __shfl_xor_sync(0xffffffffu, send2, 2);
                lacc += sqrt_approx(fmaxf(sq + fmaf(-2.f, dot, u2), 0.f));
            }
            lacc += __shfl_down_sync(0xffffffffu, lacc, 16);
            lacc += __shfl_down_sync(0xffffffffu, lacc, 8);
            lacc += __shfl_down_sync(0xffffffffu, lacc, 4);
            if (lane < 4) s_loss[w][hb + lane] = lacc;
        }
        {
            float4 m8 = *(const float4*)(&s_Mu[8][dq * 4]);
            float4 m9 = *(const float4*)(&s_Mu[9][dq * 4]);
            const float u2 = s_mu2[8 + sel];
            float lacc = 0.f;
#pragma unroll 1
            for (int k = 0; k < IH / 64; k++) {
                int i = g + k * 64;
                float4 q = *(const float4*)(ub + (size_t)(i0 + i) * RS + dq * 4);
                float  v = s_vn[i];
                float sq = v * v;
                float p8 = q.x * m8.x + q.y * m8.y + q.z * m8.z + q.w * m8.w;
                float p9 = q.x * m9.x + q.y * m9.y + q.z * m9.z + q.w * m9.w;
                float keep = sel ? p9 : p8;
                float send = sel ? p8 : p9;
                float C = keep + __shfl_xor_sync(0xffffffffu, send, 1);
                float dot = C + __shfl_xor_sync(0xffffffffu, C, 2);
                lacc += sqrt_approx(fmaxf(sq + fmaf(-2.f, dot, u2), 0.f));
            }
            lacc += __shfl_down_sync(0xffffffffu, lacc, 16);
            lacc += __shfl_down_sync(0xffffffffu, lacc, 8);
            lacc += __shfl_down_sync(0xffffffffu, lacc, 4);
            if (lane < 2) s_loss[w][8 + lane] = lacc;
        }
    }
    __syncthreads();

    if (tid < H_) {
        float l = 0.f;
#pragma unroll
        for (int ww = 0; ww < 8; ww++) l += s_loss[ww][tid];
        atomicAdd(&g_lossbuf[bo * H_ + tid], l);
    }
}

// ---------------------------------------------------------------------------
// K3: one warp per (b,o): argmin over h, emit Mu[h*] = num/den
// ---------------------------------------------------------------------------
__global__ void k3_out(float* __restrict__ out) {
    int wid  = (blockIdx.x * 256 + threadIdx.x) >> 5;
    int lane = threadIdx.x & 31;
    if (wid >= B_ * O_) return;
    float myv = 3.4e38f;
    int   myh = 0;
    if (lane < H_) { myv = g_lossbuf[wid * H_ + lane]; myh = lane; }
#pragma unroll
    for (int off = 16; off > 0; off >>= 1) {
        float ov = __shfl_xor_sync(0xffffffffu, myv, off);
        int   oh = __shfl_xor_sync(0xffffffffu, myh, off);
        if (ov < myv || (ov == myv && oh < myh)) { myv = ov; myh = oh; }
    }
    if (lane < D_)
        out[(size_t)wid * D_ + lane] =
            g_num[wid * H_ * D_ + myh * D_ + lane] / g_den[wid * H_ + myh];
}

// ---------------------------------------------------------------------------
extern "C" void kernel_launch(void* const* d_in, const int* in_sizes, int n_in,
                              void* d_out, int out_size) {
    const float* u   = (const float*)d_in[0];
    const int*   idx = (const int*)d_in[1];
    float*       out = (float*)d_out;
    (void)in_sizes; (void)n_in; (void)out_size;

    k0_zero<<<200, 256>>>((const unsigned*)idx);   // 200*256 = 51200 = |g_num|
    k1_accum<<<2 * B_ * O_, 256>>>(u, idx);
    k2_loss<<<2 * B_ * O_, 256>>>(u);
    k3_out<<<40, 256>>>(out);
}

// round 12
// speedup vs baseline: 1.0444x; 1.0444x over previous
#include <cuda_runtime.h>
#include <cstdint>

#define B_ 32
#define I_ 1152
#define IH 576          // i-half per CTA
#define O_ 10
#define D_ 16
#define H_ 10
#define S_ 922
#define T_ 512
#define PAD 20          // s_u row stride (floats)
#define RS (O_ * D_)    // 160

// dynamic smem layout (floats)
#define OFF_U    0
#define OFF_VM   (IH * PAD)            // 11520: interleaved (vn, mask)
#define OFF_NUM  (OFF_VM + 2 * IH)     // 12672: H*D partial numerators
#define OFF_DEN  (OFF_NUM + H_ * D_)   // 12832
#define OFF_LOSS (OFF_DEN + 16)        // 12848
#define SMEM_FLOATS (OFF_LOSS + 16)    // 12864 -> 51456 B

__device__ __forceinline__ float sqrt_approx(float x) {
    float y;
    asm("sqrt.approx.f32 %0, %1;" : "=f"(y) : "f"(x));
    return y;
}
__device__ __forceinline__ uint32_t mapa_peer(uint32_t addr, uint32_t rank) {
    uint32_t r;
    asm("mapa.shared::cluster.u32 %0, %1, %2;" : "=r"(r) : "r"(addr), "r"(rank));
    return r;
}
__device__ __forceinline__ float ld_cluster_f32(uint32_t addr) {
    float v;
    asm volatile("ld.shared::cluster.f32 %0, [%1];" : "=f"(v) : "r"(addr));
    return v;
}
#define CLUSTER_SYNC() do { \
    asm volatile("barrier.cluster.arrive.aligned;" ::: "memory"); \
    asm volatile("barrier.cluster.wait.aligned;"   ::: "memory"); \
} while (0)

// ---------------------------------------------------------------------------
// Cluster of 2 CTAs per (b,o); each CTA owns an i-half in smem.
//  0:  probe dtype, zero, load u half -> s_u; vn; idx scatter (range filter)
//  1:  masked accumulation -> partial num/den in smem
//  sync; peer num/den via DSMEM -> full Mu (both CTAs identical); mu2
//  2:  butterfly losses over own half -> s_lossH
//  sync; rank0 adds peer losses, argmin, writes out; final sync
// ---------------------------------------------------------------------------
__global__ void __cluster_dims__(2, 1, 1) __launch_bounds__(T_, 3)
fused_kernel(const float* __restrict__ u, const int* __restrict__ idx,
             float* __restrict__ out) {
    extern __shared__ float sm[];
    float*    s_u    = sm + OFF_U;                 // [576][PAD]
    float*    s_vm   = sm + OFF_VM;                // [576][2] (vn, mask)
    float*    s_num  = sm + OFF_NUM;               // [H][D]
    float*    s_den  = sm + OFF_DEN;               // [H]
    float*    s_lossH= sm + OFF_LOSS;              // [H]

    __shared__ __align__(16) float s_Mu[H_][D_];
    __shared__ float s_mu2[H_];
    __shared__ float s_loss[16][H_];
    __shared__ int   s_is64;

    uint32_t rank;
    asm("mov.u32 %0, %%cluster_ctarank;" : "=r"(rank));
    const int bo   = blockIdx.x >> 1;
    const int b    = bo / O_;
    const int o    = bo % O_;
    const int i0   = (int)rank * IH;
    const int tid  = threadIdx.x;
    const int lane = tid & 31;
    const int w    = tid >> 5;      // 16 warps

    const float* ub = u + ((size_t)b * I_ * O_ + o) * D_;

    // ---- phase 0: dtype probe + zero + load u half ----
    if (w == 0) {
        unsigned v = ((const unsigned*)idx)[2 * lane + 1]
                   | ((const unsigned*)idx)[2 * (lane + 32) + 1];
        unsigned r = __reduce_or_sync(0xffffffffu, v);
        if (lane == 0) s_is64 = (r == 0u) ? 1 : 0;
    }
    for (int j = tid; j < IH; j += T_) s_vm[2 * j + 1] = 0.f;
    if (tid < H_ * D_) s_num[tid] = 0.f;

    // 2304 float4 elements over 512 threads: 4.5 iters, warp-uniform tail
#pragma unroll 1
    for (int e = tid; e < IH * 4; e += T_) {
        int row = e >> 2, j = e & 3;
        float4 q = *(const float4*)(ub + (size_t)(i0 + row) * RS + j * 4);
        *(float4*)(s_u + row * PAD + j * 4) = q;
        float p = q.x * q.x + q.y * q.y + q.z * q.z + q.w * q.w;
        p += __shfl_xor_sync(0xffffffffu, p, 1);
        p += __shfl_xor_sync(0xffffffffu, p, 2);
        if (j == 0) s_vm[2 * row] = sqrt_approx(p);
    }
    __syncthreads();

    // ---- scatter (scan full idx slice, keep own half) ----
    if (s_is64) {
#pragma unroll 1
        for (int s = tid; s < S_; s += T_) {
            int base = ((b * S_ + s) * O_ + o) * H_;
            const int4* p = (const int4*)idx + (base >> 1);
            int4 a0 = p[0], a1 = p[1], a2 = p[2], a3 = p[3], a4 = p[4];
            int i;
            i = a0.x - i0; if ((unsigned)i < IH) atomicOr((unsigned*)&s_vm[2*i+1], 1u<<0);
            i = a0.z - i0; if ((unsigned)i < IH) atomicOr((unsigned*)&s_vm[2*i+1], 1u<<1);
            i = a1.x - i0; if ((unsigned)i < IH) atomicOr((unsigned*)&s_vm[2*i+1], 1u<<2);
            i = a1.z - i0; if ((unsigned)i < IH) atomicOr((unsigned*)&s_vm[2*i+1], 1u<<3);
            i = a2.x - i0; if ((unsigned)i < IH) atomicOr((unsigned*)&s_vm[2*i+1], 1u<<4);
            i = a2.z - i0; if ((unsigned)i < IH) atomicOr((unsigned*)&s_vm[2*i+1], 1u<<5);
            i = a3.x - i0; if ((unsigned)i < IH) atomicOr((unsigned*)&s_vm[2*i+1], 1u<<6);
            i = a3.z - i0; if ((unsigned)i < IH) atomicOr((unsigned*)&s_vm[2*i+1], 1u<<7);
            i = a4.x - i0; if ((unsigned)i < IH) atomicOr((unsigned*)&s_vm[2*i+1], 1u<<8);
            i = a4.z - i0; if ((unsigned)i < IH) atomicOr((unsigned*)&s_vm[2*i+1], 1u<<9);
        }
    } else {
#pragma unroll 1
        for (int s = tid; s < S_; s += T_) {
            int base = ((b * S_ + s) * O_ + o) * H_;
            const int2* p = (const int2*)idx + (base >> 1);
            int2 a0 = p[0], a1 = p[1], a2 = p[2], a3 = p[3], a4 = p[4];
            int i;
            i = a0.x - i0; if ((unsigned)i < IH) atomicOr((unsigned*)&s_vm[2*i+1], 1u<<0);
            i = a0.y - i0; if ((unsigned)i < IH) atomicOr((unsigned*)&s_vm[2*i+1], 1u<<1);
            i = a1.x - i0; if ((unsigned)i < IH) atomicOr((unsigned*)&s_vm[2*i+1], 1u<<2);
            i = a1.y - i0; if ((unsigned)i < IH) atomicOr((unsigned*)&s_vm[2*i+1], 1u<<3);
            i = a2.x - i0; if ((unsigned)i < IH) atomicOr((unsigned*)&s_vm[2*i+1], 1u<<4);
            i = a2.y - i0; if ((unsigned)i < IH) atomicOr((unsigned*)&s_vm[2*i+1], 1u<<5);
            i = a3.x - i0; if ((unsigned)i < IH) atomicOr((unsigned*)&s_vm[2*i+1], 1u<<6);
            i = a3.y - i0; if ((unsigned)i < IH) atomicOr((unsigned*)&s_vm[2*i+1], 1u<<7);
            i = a4.x - i0; if ((unsigned)i < IH) atomicOr((unsigned*)&s_vm[2*i+1], 1u<<8);
            i = a4.y - i0; if ((unsigned)i < IH) atomicOr((unsigned*)&s_vm[2*i+1], 1u<<9);
        }
    }
    __syncthreads();

    // ---- phase 1: masked accumulation over own half ----
    {
        const int d  = lane & 15;
        const int hb = (lane >> 4) * 5;
        float a0 = 0.f, a1 = 0.f, a2 = 0.f, a3 = 0.f, a4 = 0.f;
#pragma unroll 4
        for (int ii = w; ii < IH; ii += 16) {       // 36 iterations
            float2   vm = *(const float2*)&s_vm[2 * ii];
            unsigned m  = __float_as_uint(vm.y) >> hb;
            float    t0 = vm.x * s_u[ii * PAD + d];
            if (m & 1u)  a0 += t0;
            if (m & 2u)  a1 += t0;
            if (m & 4u)  a2 += t0;
            if (m & 8u)  a3 += t0;
            if (m & 16u) a4 += t0;
        }
        atomicAdd(&s_num[(hb + 0) * D_ + d], a0);
        atomicAdd(&s_num[(hb + 1) * D_ + d], a1);
        atomicAdd(&s_num[(hb + 2) * D_ + d], a2);
        atomicAdd(&s_num[(hb + 3) * D_ + d], a3);
        atomicAdd(&s_num[(hb + 4) * D_ + d], a4);
    }
    if (w < H_) {                                   // den, one h per warp
        unsigned bit = 1u << w;
        float dn = 0.f;
#pragma unroll 4
        for (int ii = lane; ii < IH; ii += 32) {    // 18 iterations
            float2 vm = *(const float2*)&s_vm[2 * ii];
            if (__float_as_uint(vm.y) & bit) dn += vm.x;
        }
#pragma unroll
        for (int off = 16; off > 0; off >>= 1)
            dn += __shfl_down_sync(0xffffffffu, dn, off);
        if (lane == 0) s_den[w] = dn;
    }
    __syncthreads();

    // ---- exchange partials with peer CTA; build full Mu ----
    CLUSTER_SYNC();
    if (tid < H_ * D_) {
        int h = tid >> 4;
        uint32_t pn = mapa_peer((uint32_t)__cvta_generic_to_shared(&s_num[tid]),
                                rank ^ 1u);
        uint32_t pd = mapa_peer((uint32_t)__cvta_generic_to_shared(&s_den[h]),
                                rank ^ 1u);
        float num = s_num[tid] + ld_cluster_f32(pn);
        float den = s_den[h]   + ld_cluster_f32(pd);
        s_Mu[h][tid & 15] = num / den;
    }
    __syncthreads();
    if (tid < H_) {
        float m2 = 0.f;
#pragma unroll
        for (int dd = 0; dd < D_; dd++) { float x = s_Mu[tid][dd]; m2 += x * x; }
        s_mu2[tid] = m2;
    }
    __syncthreads();

    // ---- phase 2: butterfly losses over own half ----
    {
        const int dq   = tid & 3;
        const int g    = tid >> 2;            // 0..127
        const int sel  = lane & 1;
        const int bit1 = (lane >> 1) & 1;

#pragma unroll 1
        for (int grp = 0; grp < 2; grp++) {
            const int hb = grp * 4;
            float4 mq0 = *(const float4*)(&s_Mu[hb + 0][dq * 4]);
            float4 mq1 = *(const float4*)(&s_Mu[hb + 1][dq * 4]);
            float4 mq2 = *(const float4*)(&s_Mu[hb + 2][dq * 4]);
            float4 mq3 = *(const float4*)(&s_Mu[hb + 3][dq * 4]);
            const float u2 = s_mu2[hb + 2 * bit1 + sel];
            float lacc = 0.f;
#pragma unroll 1
            for (int k = 0; k < 5; k++) {           // 4.5 iters, warp-uniform tail
                int i = g + k * 128;
                if (i < IH) {
                    float4 q = *(const float4*)(s_u + i * PAD + dq * 4);
                    float  v = s_vm[2 * i];
                    float sq = v * v;
                    float p0 = q.x*mq0.x + q.y*mq0.y + q.z*mq0.z + q.w*mq0.w;
                    float p1 = q.x*mq1.x + q.y*mq1.y + q.z*mq1.z + q.w*mq1.w;
                    float p2 = q.x*mq2.x + q.y*mq2.y + q.z*mq2.z + q.w*mq2.w;
                    float p3 = q.x*mq3.x + q.y*mq3.y + q.z*mq3.z + q.w*mq3.w;
                    float keep_lo = sel ? p1 : p0;
                    float send_lo = sel ? p0 : p1;
                    float C_lo = keep_lo + __shfl_xor_sync(0xffffffffu, send_lo, 1);
                    float keep_hi = sel ? p3 : p2;
                    float send_hi = sel ? p2 : p3;
                    float C_hi = keep_hi + __shfl_xor_sync(0xffffffffu, send_hi, 1);
                    float keep2 = bit1 ? C_hi : C_lo;
                    float send2 = bit1 ? C_lo : C_hi;
                    float dot = keep2 + __shfl_xor_sync(0xffffffffu, send2, 2);
                    lacc += sqrt_approx(fmaxf(sq + fmaf(-2.f, dot, u2), 0.f));
                }
            }
            lacc += __shfl_down_sync(0xffffffffu, lacc, 16);
            lacc += __shfl_down_sync(0xffffffffu, lacc, 8);
            lacc += __shfl_down_sync(0xffffffffu, lacc, 4);
            if (lane < 4) s_loss[w][hb + lane] = lacc;
        }
        {
            float4 m8 = *(const float4*)(&s_Mu[8][dq * 4]);
            float4 m9 = *(const float4*)(&s_Mu[9][dq * 4]);
            const float u2 = s_mu2[8 + sel];
            float lacc = 0.f;
#pragma unroll 1
            for (int k = 0; k < 5; k++) {
                int i = g + k * 128;
                if (i < IH) {
                    float4 q = *(const float4*)(s_u + i * PAD + dq * 4);
                    float  v = s_vm[2 * i];
                    float sq = v * v;
                    float p8 = q.x*m8.x + q.y*m8.y + q.z*m8.z + q.w*m8.w;
                    float p9 = q.x*m9.x + q.y*m9.y + q.z*m9.z + q.w*m9.w;
                    float keep = sel ? p9 : p8;
                    float send = sel ? p8 : p9;
                    float C = keep + __shfl_xor_sync(0xffffffffu, send, 1);
                    float dot = C + __shfl_xor_sync(0xffffffffu, C, 2);
                    lacc += sqrt_approx(fmaxf(sq + fmaf(-2.f, dot, u2), 0.f));
                }
            }
            lacc += __shfl_down_sync(0xffffffffu, lacc, 16);
            lacc += __shfl_down_sync(0xffffffffu, lacc, 8);
            lacc += __shfl_down_sync(0xffffffffu, lacc, 4);
            if (lane < 2) s_loss[w][8 + lane] = lacc;
        }
    }
    __syncthreads();
    if (tid < H_) {
        float l = 0.f;
#pragma unroll
        for (int ww = 0; ww < 16; ww++) l += s_loss[ww][tid];
        s_lossH[tid] = l;
    }
    __syncthreads();

    // ---- exchange loss halves; rank 0 argmin + output ----
    CLUSTER_SYNC();
    if (rank == 0 && w == 0) {
        float myv = 3.4e38f;
        int   myh = 0;
        if (lane < H_) {
            uint32_t pl = mapa_peer(
                (uint32_t)__cvta_generic_to_shared(&s_lossH[lane]), 1u);
            myv = s_lossH[lane] + ld_cluster_f32(pl);
            myh = lane;
        }
#pragma unroll
        for (int off = 16; off > 0; off >>= 1) {
            float ov = __shfl_xor_sync(0xffffffffu, myv, off);
            int   oh = __shfl_xor_sync(0xffffffffu, myh, off);
            if (ov < myv || (ov == myv && oh < myh)) { myv = ov; myh = oh; }
        }
        if (lane < D_) out[(size_t)bo * D_ + lane] = s_Mu[myh][lane];
    }
    CLUSTER_SYNC();   // peer smem must outlive rank0's reads
}

// ---------------------------------------------------------------------------
extern "C" void kernel_launch(void* const* d_in, const int* in_sizes, int n_in,
                              void* d_out, int out_size) {
    const float* u   = (const float*)d_in[0];
    const int*   idx = (const int*)d_in[1];
    float*       out = (float*)d_out;
    (void)in_sizes; (void)n_in; (void)out_size;

    const int dynSmem = SMEM_FLOATS * 4;   // 51456 bytes
    static int attr_set = 0;
    if (!attr_set) {
        cudaFuncSetAttribute(fused_kernel,
                             cudaFuncAttributeMaxDynamicSharedMemorySize, dynSmem);
        attr_set = 1;
    }
    fused_kernel<<<2 * B_ * O_, T_, dynSmem>>>(u, idx, out);
}